// round 11
// baseline (speedup 1.0000x reference)
#include <cuda_runtime.h>
#include <cstdint>

// out[p] = (L >= 0) || (missing(p) - L >= 0.5), written as float 0.0/1.0
// L = 7-point Laplacian (6*center - face neighbors, zero padding);
// missing(p) = count of out-of-grid face neighbors (kernel sums to 0, so
// conv(1-m,k) = missing(p) - conv(m,k)).
//
// R10 (rolling-z x-quad, KZ=6, __stcs, shuffle x-halo) with the arithmetic
// reformulated to cut issue slots:
//   - never form L: compare g = 6*B against s = sum(neighbors) directly:
//       L >= 0        <=>  g >= s
//       miss-L >= 0.5 <=>  g <= s + (miss - 0.5)
//     -> or-combined FSETP pairs + FSEL, no final FADD/LOP.
//   - packed f32x2 adds/muls (PTX-only on Blackwell) for the neighbor sums;
//     float4 loads give naturally paired registers.

#define DSZ 192
#define KZ  6
#define ZT  (DSZ / KZ)   // 32 z-tiles

#define ADD2(d, a, b) asm("add.rn.f32x2 %0, %1, %2;" : "=l"(d) : "l"(a), "l"(b))
#define MUL2(d, a, b) asm("mul.rn.f32x2 %0, %1, %2;" : "=l"(d) : "l"(a), "l"(b))
#define PACK2(d, lo, hi) asm("mov.b64 %0, {%1, %2};" : "=l"(d) : "f"(lo), "f"(hi))
#define UNPACK2(lo, hi, s) asm("mov.b64 {%0, %1}, %2;" : "=f"(lo), "=f"(hi) : "l"(s))

__global__ __launch_bounds__(384, 4) void mask_kernel(
    const float* __restrict__ m, float* __restrict__ out)
{
    const int tx = threadIdx.x;                       // 0..47 -> x quad
    const int y  = blockIdx.y * blockDim.y + threadIdx.y;
    const int zb = blockIdx.z;
    const int z0 = (zb & (ZT - 1)) * KZ;
    const int b  = zb / ZT;
    const int x0 = tx * 4;
    const int lane = (threadIdx.y * 48 + tx) & 31;

    const size_t plane = (size_t)DSZ * DSZ;
    const float* p = m + (((size_t)b * DSZ + z0) * DSZ + y) * DSZ + x0;
    float* q = out + (((size_t)b * DSZ + z0) * DSZ + y) * DSZ + x0;

    const float4 zero4 = make_float4(0.f, 0.f, 0.f, 0.f);
    const bool hasYm = (y > 0);
    const bool hasYp = (y < DSZ - 1);
    const bool hasXl = (x0 > 0);
    const bool hasXr = (x0 + 4 < DSZ);
    const bool edgeL = hasXl && (lane == 0);
    const bool edgeR = hasXr && (lane == 31);

    // thresholds: miss - 0.5 per output lane (interior-z part), packed
    const float missY = (float)((int)(!hasYm) + (int)(!hasYp));
    const float f0b = missY + (float)(int)(!hasXl) - 0.5f;
    const float fmb = missY - 0.5f;
    const float f3b = missY + (float)(int)(!hasXr) - 0.5f;
    uint64_t th01_base, th23_base, six2;
    PACK2(th01_base, f0b, fmb);
    PACK2(th23_base, fmb, f3b);
    PACK2(six2, 6.f, 6.f);

    float4 A = (z0 > 0) ? *(const float4*)(p - plane) : zero4;  // z-1
    float4 B = *(const float4*)(p);                              // z

    #pragma unroll
    for (int iz = 0; iz < KZ; ++iz) {
        const int z = z0 + iz;
        float4 C = (z < DSZ - 1) ? *(const float4*)(p + plane) : zero4;  // z+1
        float4 ym = hasYm ? *(const float4*)(p - DSZ) : zero4;
        float4 yp = hasYp ? *(const float4*)(p + DSZ) : zero4;

        float xls = __shfl_up_sync(0xffffffffu, B.w, 1);
        float xrs = __shfl_down_sync(0xffffffffu, B.x, 1);
        float xl = 0.f, xr = 0.f;
        if (hasXl) xl = edgeL ? __ldg(p - 1) : xls;
        if (hasXr) xr = edgeR ? __ldg(p + 4) : xrs;

        // packed neighbor sums
        uint64_t ym01, ym23, yp01, yp23, A01, A23, C01, C23, B01, B23;
        PACK2(ym01, ym.x, ym.y); PACK2(ym23, ym.z, ym.w);
        PACK2(yp01, yp.x, yp.y); PACK2(yp23, yp.z, yp.w);
        PACK2(A01, A.x, A.y);    PACK2(A23, A.z, A.w);
        PACK2(C01, C.x, C.y);    PACK2(C23, C.z, C.w);
        PACK2(B01, B.x, B.y);    PACK2(B23, B.z, B.w);
        uint64_t PA, PM, PB;                 // x-shifted pairs
        PACK2(PA, xl, B.x);                  // (-x for L0 | -x for L1)
        PACK2(PM, B.y, B.z);                 // (+x for L0 | +x for L1) == (-x for L2 | -x for L3)
        PACK2(PB, B.w, xr);                  // (+x for L2 | +x for L3)

        uint64_t t, u, s01, s23, x01, x23, g01, g23;
        ADD2(t, ym01, yp01); ADD2(u, A01, C01); ADD2(s01, t, u);
        ADD2(x01, PA, PM);   ADD2(s01, s01, x01);
        ADD2(t, ym23, yp23); ADD2(u, A23, C23); ADD2(s23, t, u);
        ADD2(x23, PM, PB);   ADD2(s23, s23, x23);
        MUL2(g01, B01, six2);
        MUL2(g23, B23, six2);

        // z-boundary threshold bump (dead code for interior iterations)
        uint64_t th01 = th01_base, th23 = th23_base;
        float mz = 0.f;
        if (iz == 0)      mz += (z0 == 0)         ? 1.f : 0.f;
        if (iz == KZ - 1) mz += (z0 == DSZ - KZ)  ? 1.f : 0.f;
        if (mz != 0.f) {
            uint64_t mzp; PACK2(mzp, mz, mz);
            ADD2(th01, th01, mzp);
            ADD2(th23, th23, mzp);
        }
        uint64_t st01, st23;
        ADD2(st01, s01, th01);
        ADD2(st23, s23, th23);

        float g0, g1, g2, g3, s0, s1, s2, s3, t0, t1, t2, t3;
        UNPACK2(g0, g1, g01); UNPACK2(g2, g3, g23);
        UNPACK2(s0, s1, s01); UNPACK2(s2, s3, s23);
        UNPACK2(t0, t1, st01); UNPACK2(t2, t3, st23);

        float4 o;
        o.x = ((g0 >= s0) | (g0 <= t0)) ? 1.f : 0.f;
        o.y = ((g1 >= s1) | (g1 <= t1)) ? 1.f : 0.f;
        o.z = ((g2 >= s2) | (g2 <= t2)) ? 1.f : 0.f;
        o.w = ((g3 >= s3) | (g3 <= t3)) ? 1.f : 0.f;

        __stcs((float4*)q, o);

        A = B; B = C;
        p += plane; q += plane;
    }
}

extern "C" void kernel_launch(void* const* d_in, const int* in_sizes, int n_in,
                              void* d_out, int out_size)
{
    const float* m = (const float*)d_in[0];
    float* out = (float*)d_out;

    dim3 block(48, 8, 1);                 // 384 threads: full row x 8 rows
    dim3 grid(1, DSZ / 8, 2 * ZT);        // y-tiles, (batch * z-tiles)
    mask_kernel<<<grid, block>>>(m, out);
}